// round 11
// baseline (speedup 1.0000x reference)
#include <cuda_runtime.h>
#include <cuda_fp16.h>
#include <math.h>
#include <stdint.h>

#define NTOK 4096
#define DMODEL 1024
#define D3 (3 * DMODEL)
#define NPART 64   // partials per row = (NTOK/BN) tiles * 2 col-warps

// Scratch (no cudaMalloc allowed)
__device__ __half g_Xh[NTOK * DMODEL];
__device__ __half g_Wt[D3 * DMODEL];
__device__ float  g_bcat[D3];
__device__ __half g_QKV[NTOK * D3];
__device__ __half g_Vt[DMODEL * NTOK];
__device__ __half g_E[(size_t)NTOK * NTOK];
__device__ float  g_rsp[(size_t)NTOK * NPART];
__device__ float  g_rowsum[NTOK];

// ---------------------------------------------------------------------------
__device__ __forceinline__ void cp_async16(uint32_t smem_addr, const void* gptr) {
    asm volatile("cp.async.cg.shared.global [%0], [%1], 16;\n"
                 :: "r"(smem_addr), "l"(gptr));
}

__device__ __forceinline__ void ldmatrix_x4(uint32_t& r0, uint32_t& r1,
                                            uint32_t& r2, uint32_t& r3,
                                            uint32_t addr) {
    asm volatile("ldmatrix.sync.aligned.m8n8.x4.shared.b16 {%0,%1,%2,%3}, [%4];"
                 : "=r"(r0), "=r"(r1), "=r"(r2), "=r"(r3) : "r"(addr));
}

__device__ __forceinline__ void mma_f16(float (&d)[4], const uint32_t (&a)[4],
                                        uint32_t b0, uint32_t b1) {
    asm volatile(
        "mma.sync.aligned.m16n8k16.row.col.f32.f16.f16.f32 "
        "{%0,%1,%2,%3}, {%4,%5,%6,%7}, {%8,%9}, {%0,%1,%2,%3};"
        : "+f"(d[0]), "+f"(d[1]), "+f"(d[2]), "+f"(d[3])
        : "r"(a[0]), "r"(a[1]), "r"(a[2]), "r"(a[3]), "r"(b0), "r"(b1));
}

__device__ __forceinline__ void mbar_init(uint32_t addr, uint32_t count) {
    asm volatile("mbarrier.init.shared.b64 [%0], %1;" :: "r"(addr), "r"(count) : "memory");
}
__device__ __forceinline__ void mbar_arrive(uint32_t addr) {
    asm volatile("mbarrier.arrive.shared.b64 _, [%0];" :: "r"(addr) : "memory");
}
__device__ __forceinline__ void cpasync_mbar_arrive(uint32_t addr) {
    asm volatile("cp.async.mbarrier.arrive.noinc.shared.b64 [%0];" :: "r"(addr) : "memory");
}
__device__ __forceinline__ void mbar_wait_parity(uint32_t addr, uint32_t parity) {
    uint32_t done;
    asm volatile(
        "{\n\t.reg .pred p;\n\t"
        "mbarrier.try_wait.parity.acquire.cta.shared::cta.b64 p, [%1], %2;\n\t"
        "selp.b32 %0, 1, 0, p;\n\t}"
        : "=r"(done) : "r"(addr), "r"(parity) : "memory");
    if (!done) {
        asm volatile(
            "{\n\t.reg .pred P1;\n\t"
            "WAIT_LOOP_%=:\n\t"
            "mbarrier.try_wait.parity.acquire.cta.shared::cta.b64 P1, [%0], %1, 0x989680;\n\t"
            "@P1 bra.uni WAIT_DONE_%=;\n\t"
            "bra.uni WAIT_LOOP_%=;\n\t"
            "WAIT_DONE_%=:\n\t}"
            :: "r"(addr), "r"(parity) : "memory");
    }
}

// ---------------------------------------------------------------------------
// Warp-specialized persistent fp16 NT GEMM.
// 192 threads: warps 0-3 consumers (64x64 warp tiles of a 128x128 CTA tile),
// warps 4-5 producers (all cp.asyncs). 6-stage smem ring, mbarrier handshake,
// NO __syncthreads in the mainloop. 1 CTA/SM, 148 persistent CTAs.
// MODE 0: +bias half out. MODE 1: exp() half out + partial rowsums.
// MODE 2: f32 out scaled by 1/rowsum[row].
// ---------------------------------------------------------------------------
#define BM 128
#define BN 128
#define BKH 64
#define A_BYTES (BM * 128)
#define B_BYTES (BN * 128)
#define STAGE_BYTES (A_BYTES + B_BYTES)       // 32768
#define NS 6
#define STAGE0_OFF 128
#define GEMM_SMEM (STAGE0_OFF + NS * STAGE_BYTES)   // 196736
#define PGRID 148

__device__ __forceinline__ uint32_t swz(int row, int c8) {
    return (uint32_t)(row * 128 + ((c8 ^ (row & 7)) << 4));
}

template <int MODE>
__global__ __launch_bounds__(192, 1)
void hgemm_nt(const __half* __restrict__ A, int lda,
              const __half* __restrict__ Bp, int ldb,
              const float* __restrict__ aux,      // bias (0) / rowsum (2)
              float* __restrict__ rsp,            // partial rowsums (1)
              void* __restrict__ Cv, int ldc,
              int nbm, int nbn, int K, int N, float alpha)
{
    extern __shared__ __align__(128) char smem[];
    const uint32_t sb = (uint32_t)__cvta_generic_to_shared(smem);
    const uint32_t full0 = sb;            // 6 x 8B
    const uint32_t empty0 = sb + 64;      // 6 x 8B
    const uint32_t stage0 = sb + STAGE0_OFF;
    const int tid = threadIdx.x, lane = tid & 31, warp = tid >> 5;
    const int nch = K / BKH;
    const int ntiles = nbm * nbn;

    if (tid == 0) {
        for (int s = 0; s < NS; s++) {
            mbar_init(full0 + 8 * s, 64);   // 64 producer-thread cp.async arrivals
            mbar_init(empty0 + 8 * s, 4);   // 4 consumer-warp arrivals
        }
    }
    __syncthreads();   // only sync in the kernel: after mbarrier init

    if (warp >= 4) {
        // ----------------- producer (warps 4,5; 64 threads) -----------------
        const int pt = tid - 128;          // 0..63
        uint32_t gs = 0;
        for (int t = blockIdx.x; t < ntiles; t += gridDim.x) {
            const int bm = (t / nbn) * BM;
            const int bn = (t % nbn) * BN;
            for (int c = 0; c < nch; c++, gs++) {
                const int s = gs % NS;
                const uint32_t u = gs / NS;
                if (u > 0) mbar_wait_parity(empty0 + 8 * s, (u - 1) & 1);
                const int k0 = c * BKH;
                const uint32_t abase = stage0 + s * STAGE_BYTES;
                const uint32_t bbase = abase + A_BYTES;
#pragma unroll
                for (int i = 0; i < 16; i++) {       // A: 1024 x 16B
                    int id = i * 64 + pt;
                    int row = id >> 3, c8 = id & 7;
                    cp_async16(abase + swz(row, c8),
                               A + (size_t)(bm + row) * lda + k0 + c8 * 8);
                }
#pragma unroll
                for (int i = 0; i < 16; i++) {       // B: 1024 x 16B
                    int id = i * 64 + pt;
                    int row = id >> 3, c8 = id & 7;
                    cp_async16(bbase + swz(row, c8),
                               Bp + (size_t)(bn + row) * ldb + k0 + c8 * 8);
                }
                cpasync_mbar_arrive(full0 + 8 * s);
            }
        }
        return;
    }

    // ------------------- consumer (warps 0-3; 128 threads) -------------------
    const int wm = (warp >> 1) * 64, wn = (warp & 1) * 64;
    uint32_t gs = 0;

    for (int t = blockIdx.x; t < ntiles; t += gridDim.x) {
        const int bm = (t / nbn) * BM;
        const int tn = t % nbn;
        const int bn = tn * BN;

        float acc[4][8][4];
#pragma unroll
        for (int i = 0; i < 4; i++)
#pragma unroll
            for (int j = 0; j < 8; j++)
#pragma unroll
                for (int v = 0; v < 4; v++) acc[i][j][v] = 0.0f;

        for (int c = 0; c < nch; c++, gs++) {
            const int s = gs % NS;
            mbar_wait_parity(full0 + 8 * s, (gs / NS) & 1);
            const uint32_t abase = stage0 + s * STAGE_BYTES;
            const uint32_t bbase = abase + A_BYTES;

            uint32_t af[2][4][4];
            uint32_t bf[4][4];

            // fragment load helpers
            auto LA = [&](int buf, int ks) {
#pragma unroll
                for (int mt = 0; mt < 4; mt++) {
                    int row = wm + mt * 16 + (lane & 15);
                    int c8  = 2 * ks + (lane >> 4);
                    ldmatrix_x4(af[buf][mt][0], af[buf][mt][1],
                                af[buf][mt][2], af[buf][mt][3],
                                abase + swz(row, c8));
                }
            };
            auto LB = [&](int p, int ks) {
                int row = wn + p * 16 + (lane & 7) + ((lane >> 4) << 3);
                int c8  = 2 * ks + ((lane >> 3) & 1);
                ldmatrix_x4(bf[p][0], bf[p][1], bf[p][2], bf[p][3],
                            bbase + swz(row, c8));
            };
            auto MM = [&](int buf, int p) {
#pragma unroll
                for (int mt = 0; mt < 4; mt++) {
                    mma_f16(acc[mt][2 * p],     af[buf][mt], bf[p][0], bf[p][1]);
                    mma_f16(acc[mt][2 * p + 1], af[buf][mt], bf[p][2], bf[p][3]);
                }
            };

            // software-pipelined chunk: bf[p+1] prefetched under batch p,
            // af double-buffered across ks, bf[0] of next ks under batch 2/3.
            LA(0, 0); LB(0, 0);
#pragma unroll
            for (int ks = 0; ks < 4; ks++) {
                const int cur = ks & 1;
                LB(1, ks);  MM(cur, 0);
                LB(2, ks);  MM(cur, 1);
                if (ks < 3) LA(cur ^ 1, ks + 1);
                LB(3, ks);  MM(cur, 2);
                if (ks < 3) LB(0, ks + 1);
                MM(cur, 3);
            }

            __syncwarp();
            if (lane == 0) mbar_arrive(empty0 + 8 * s);
        }

        // epilogue (identical math to round 8)
        const int r0 = lane >> 2, cc = (lane & 3) * 2;
#pragma unroll
        for (int mt = 0; mt < 4; mt++) {
            const int row = bm + wm + mt * 16 + r0;
            float inv0 = 1.0f, inv1 = 1.0f;
            if (MODE == 2) { inv0 = 1.0f / aux[row]; inv1 = 1.0f / aux[row + 8]; }
            float s0 = 0.0f, s1 = 0.0f;
#pragma unroll
            for (int nt = 0; nt < 8; nt++) {
                const int col = bn + wn + nt * 8 + cc;
                float v0 = acc[mt][nt][0] * alpha;
                float v1 = acc[mt][nt][1] * alpha;
                float v2 = acc[mt][nt][2] * alpha;
                float v3 = acc[mt][nt][3] * alpha;
                if (MODE == 0) {
                    float b0 = aux[col], b1 = aux[col + 1];
                    v0 += b0; v1 += b1; v2 += b0; v3 += b1;
                    __half* C = (__half*)Cv;
                    *reinterpret_cast<__half2*>(C + (size_t)row * ldc + col) = __floats2half2_rn(v0, v1);
                    *reinterpret_cast<__half2*>(C + (size_t)(row + 8) * ldc + col) = __floats2half2_rn(v2, v3);
                } else if (MODE == 1) {
                    v0 = __expf(v0); v1 = __expf(v1); v2 = __expf(v2); v3 = __expf(v3);
                    s0 += v0 + v1;  s1 += v2 + v3;
                    __half* C = (__half*)Cv;
                    *reinterpret_cast<__half2*>(C + (size_t)row * ldc + col) = __floats2half2_rn(v0, v1);
                    *reinterpret_cast<__half2*>(C + (size_t)(row + 8) * ldc + col) = __floats2half2_rn(v2, v3);
                } else {
                    float* C = (float*)Cv;
                    *reinterpret_cast<float2*>(C + (size_t)row * ldc + col) =
                        make_float2(v0 * inv0, v1 * inv0);
                    *reinterpret_cast<float2*>(C + (size_t)(row + 8) * ldc + col) =
                        make_float2(v2 * inv1, v3 * inv1);
                }
            }
            if (MODE == 1) {
                s0 += __shfl_xor_sync(~0u, s0, 1); s0 += __shfl_xor_sync(~0u, s0, 2);
                s1 += __shfl_xor_sync(~0u, s1, 1); s1 += __shfl_xor_sync(~0u, s1, 2);
                if ((lane & 3) == 0) {
                    const int part = tn * 2 + (warp & 1);
                    rsp[(size_t)row * NPART + part] = s0;
                    rsp[(size_t)(row + 8) * NPART + part] = s1;
                }
            }
        }
    }
}

// ---------------------------------------------------------------------------
// Fused prep (one launch): x->half, 3 W transposes (f32->half), bias concat.
// ---------------------------------------------------------------------------
__global__ __launch_bounds__(256)
void prep_kernel(const float* __restrict__ x,
                 const float* __restrict__ Wq, const float* __restrict__ Wk,
                 const float* __restrict__ Wv,
                 const float* __restrict__ bq, const float* __restrict__ bk,
                 const float* __restrict__ bv,
                 __half* __restrict__ Xh, __half* __restrict__ Wt,
                 float* __restrict__ bcat)
{
    const int bid = blockIdx.x;
    const int tid = threadIdx.x;

    if (bid < 3072) {
        __shared__ float t[32][33];
        const int which = bid >> 10;
        const int tile  = bid & 1023;
        const int bx = (tile & 31) * 32;
        const int by = (tile >> 5) * 32;
        const float* W = (which == 0) ? Wq : (which == 1) ? Wk : Wv;
        __half* out = Wt + (size_t)which * DMODEL * DMODEL;
        const int xl = tid & 31, yl = tid >> 5;
#pragma unroll
        for (int i = yl; i < 32; i += 8)
            t[i][xl] = W[(size_t)(by + i) * DMODEL + bx + xl];
        __syncthreads();
#pragma unroll
        for (int i = yl; i < 32; i += 8)
            out[(size_t)(bx + i) * DMODEL + by + xl] = __float2half_rn(t[xl][i]);
    } else if (bid < 4096) {
        const int n4 = NTOK * DMODEL / 4;
        int i = (bid - 3072) * 256 + tid;
        for (; i < n4; i += 1024 * 256) {
            float4 v = reinterpret_cast<const float4*>(x)[i];
            __half2* o = reinterpret_cast<__half2*>(Xh) + 2 * i;
            o[0] = __floats2half2_rn(v.x, v.y);
            o[1] = __floats2half2_rn(v.z, v.w);
        }
    } else {
        for (int i = tid; i < D3; i += 256) {
            float v = (i < DMODEL) ? bq[i]
                    : (i < 2 * DMODEL) ? bk[i - DMODEL]
                    : bv[i - 2 * DMODEL];
            bcat[i] = v;
        }
    }
}

__global__ __launch_bounds__(256)
void transpose_h2h_kernel(const __half* __restrict__ in, int ldin,
                          __half* __restrict__ out, int R, int C)
{
    __shared__ __half t[32][33];
    const int bx = blockIdx.x * 32, by = blockIdx.y * 32;
    const int x = threadIdx.x;
#pragma unroll
    for (int i = threadIdx.y; i < 32; i += 8)
        t[i][x] = in[(size_t)(by + i) * ldin + bx + x];
    __syncthreads();
#pragma unroll
    for (int i = threadIdx.y; i < 32; i += 8)
        out[(size_t)(bx + i) * R + by + x] = t[x][i];
}

__global__ __launch_bounds__(256)
void rowsum_reduce_kernel(const float* __restrict__ rsp, float* __restrict__ rs)
{
    int row = blockIdx.x * 256 + threadIdx.x;
    if (row < NTOK) {
        float s = 0.0f;
#pragma unroll 16
        for (int i = 0; i < NPART; i++) s += rsp[(size_t)row * NPART + i];
        rs[row] = s;
    }
}

// ---------------------------------------------------------------------------
extern "C" void kernel_launch(void* const* d_in, const int* in_sizes, int n_in,
                              void* d_out, int out_size)
{
    const float* x  = (const float*)d_in[0];
    const float* Wq = (const float*)d_in[1];
    const float* Wk = (const float*)d_in[2];
    const float* Wv = (const float*)d_in[3];
    const float* bq = (const float*)d_in[4];
    const float* bk = (const float*)d_in[5];
    const float* bv = (const float*)d_in[6];
    float* out = (float*)d_out;

    __half *Xh, *Wt, *QKV, *Vt, *E;
    float *bcat, *rsp, *rowsum;
    cudaGetSymbolAddress((void**)&Xh,     g_Xh);
    cudaGetSymbolAddress((void**)&Wt,     g_Wt);
    cudaGetSymbolAddress((void**)&bcat,   g_bcat);
    cudaGetSymbolAddress((void**)&QKV,    g_QKV);
    cudaGetSymbolAddress((void**)&Vt,     g_Vt);
    cudaGetSymbolAddress((void**)&E,      g_E);
    cudaGetSymbolAddress((void**)&rsp,    g_rsp);
    cudaGetSymbolAddress((void**)&rowsum, g_rowsum);

    const int M = NTOK, D = DMODEL;

    cudaFuncSetAttribute(hgemm_nt<0>, cudaFuncAttributeMaxDynamicSharedMemorySize, GEMM_SMEM);
    cudaFuncSetAttribute(hgemm_nt<1>, cudaFuncAttributeMaxDynamicSharedMemorySize, GEMM_SMEM);
    cudaFuncSetAttribute(hgemm_nt<2>, cudaFuncAttributeMaxDynamicSharedMemorySize, GEMM_SMEM);

    // 1. fused prep
    prep_kernel<<<4097, 256>>>(x, Wq, Wk, Wv, bq, bk, bv, Xh, Wt, bcat);

    // 2. fused QKV projection (persistent, warp-specialized)
    hgemm_nt<0><<<PGRID, 192, GEMM_SMEM>>>(Xh, D, Wt, D, bcat, nullptr,
                                           QKV, D3, M / BM, D3 / BN, D, D3, 1.0f);

    // 3. V^T
    {
        dim3 g(D / 32, M / 32), t(32, 8);
        transpose_h2h_kernel<<<g, t>>>(QKV + 2 * D, D3, Vt, M, D);
    }

    // 4. E = exp(Q K^T / 32), partial rowsums
    hgemm_nt<1><<<PGRID, 192, GEMM_SMEM>>>(QKV + 0 * D, D3, QKV + 1 * D, D3,
                                           nullptr, rsp, E, M,
                                           M / BM, M / BN, D, M, 1.0f / 32.0f);

    // 5. reduce partials
    rowsum_reduce_kernel<<<(M + 255) / 256, 256>>>(rsp, rowsum);

    // 6. out = (E @ Vt^T) / rowsum
    hgemm_nt<2><<<PGRID, 192, GEMM_SMEM>>>(E, M, Vt, M, rowsum, nullptr,
                                           out, D, M / BM, D / BN, M, D, 1.0f);
}

// round 12
// speedup vs baseline: 1.0916x; 1.0916x over previous
#include <cuda_runtime.h>
#include <cuda_fp16.h>
#include <math.h>
#include <stdint.h>

#define NTOK 4096
#define DMODEL 1024
#define D3 (3 * DMODEL)
#define NPART 64   // partials per row = (NTOK/BN) tiles * 2 col-warps

// Scratch (no cudaMalloc allowed)
__device__ __half g_Xh[NTOK * DMODEL];
__device__ __half g_Wt[D3 * DMODEL];
__device__ float  g_bcat[D3];
__device__ __half g_QKV[NTOK * D3];
__device__ __half g_E[(size_t)NTOK * NTOK];
__device__ float  g_rsp[(size_t)NTOK * NPART];
__device__ float  g_rowsum[NTOK];

// ---------------------------------------------------------------------------
__device__ __forceinline__ void cp_async16(uint32_t smem_addr, const void* gptr) {
    asm volatile("cp.async.cg.shared.global [%0], [%1], 16;\n"
                 :: "r"(smem_addr), "l"(gptr));
}
__device__ __forceinline__ void cp_commit() {
    asm volatile("cp.async.commit_group;\n");
}
template <int N>
__device__ __forceinline__ void cp_wait() {
    asm volatile("cp.async.wait_group %0;\n" :: "n"(N));
}

__device__ __forceinline__ void ldmatrix_x4(uint32_t& r0, uint32_t& r1,
                                            uint32_t& r2, uint32_t& r3,
                                            uint32_t addr) {
    asm volatile("ldmatrix.sync.aligned.m8n8.x4.shared.b16 {%0,%1,%2,%3}, [%4];"
                 : "=r"(r0), "=r"(r1), "=r"(r2), "=r"(r3) : "r"(addr));
}

__device__ __forceinline__ void ldmatrix_x4_trans(uint32_t& r0, uint32_t& r1,
                                                  uint32_t& r2, uint32_t& r3,
                                                  uint32_t addr) {
    asm volatile("ldmatrix.sync.aligned.m8n8.x4.trans.shared.b16 {%0,%1,%2,%3}, [%4];"
                 : "=r"(r0), "=r"(r1), "=r"(r2), "=r"(r3) : "r"(addr));
}

__device__ __forceinline__ void mma_f16(float (&d)[4], const uint32_t (&a)[4],
                                        uint32_t b0, uint32_t b1) {
    asm volatile(
        "mma.sync.aligned.m16n8k16.row.col.f32.f16.f16.f32 "
        "{%0,%1,%2,%3}, {%4,%5,%6,%7}, {%8,%9}, {%0,%1,%2,%3};"
        : "+f"(d[0]), "+f"(d[1]), "+f"(d[2]), "+f"(d[3])
        : "r"(a[0]), "r"(a[1]), "r"(a[2]), "r"(a[3]), "r"(b0), "r"(b1));
}

// ---------------------------------------------------------------------------
// Persistent fp16 GEMM (round-10 config: 128 thr, 4 warps, 64x64 warp tiles,
// CTA tile 128x128, BK=64, 3 stages, 2 CTAs/SM, 296 persistent CTAs).
// MODE 0: +bias half out. MODE 1: exp() half out + partial rowsums.
// MODE 2: f32 out scaled by 1/rowsum[row].
// VB=false: B' is [N,K] k-major (NT, regular ldmatrix).
// VB=true:  B  is [K,N] natural layout (V); fragments via ldmatrix.trans.
// ---------------------------------------------------------------------------
#define BM 128
#define BN 128
#define BKH 64
#define A_BYTES (BM * 128)
#define B_BYTES (BN * 128)                  // == 64 rows * 256B for VB tiles
#define STAGE_BYTES (A_BYTES + B_BYTES)     // 32768
#define STAGES 3
#define GEMM_SMEM (STAGES * STAGE_BYTES)    // 98304
#define PGRID 296

__device__ __forceinline__ uint32_t swz(int row, int c8) {
    return (uint32_t)(row * 128 + ((c8 ^ (row & 7)) << 4));
}
// 256-byte-row swizzle (for natural-layout V tiles: 64 k-rows x 256B)
__device__ __forceinline__ uint32_t swz256(int row, int c16) {
    return (uint32_t)(row * 256 + ((c16 ^ (row & 7)) << 4));
}

template <int MODE, bool VB>
__global__ __launch_bounds__(128, 2)
void hgemm_nt(const __half* __restrict__ A, int lda,
              const __half* __restrict__ Bp, int ldb,
              const float* __restrict__ aux,      // bias (0) / rowsum (2)
              float* __restrict__ rsp,            // partial rowsums (1)
              void* __restrict__ Cv, int ldc,
              int nbm, int nbn, int K, int N, float alpha)
{
    extern __shared__ __align__(1024) char smem[];
    const uint32_t sb = (uint32_t)__cvta_generic_to_shared(smem);
    const int tid = threadIdx.x, lane = tid & 31, warp = tid >> 5;
    const int wm = (warp >> 1) * 64, wn = (warp & 1) * 64;
    const int nch = K / BKH;
    const int ntiles = nbm * nbn;

    for (int t = blockIdx.x; t < ntiles; t += gridDim.x) {
        const int bm = (t / nbn) * BM;
        const int tn = t % nbn;
        const int bn = tn * BN;

        float acc[4][8][4];
#pragma unroll
        for (int i = 0; i < 4; i++)
#pragma unroll
            for (int j = 0; j < 8; j++)
#pragma unroll
                for (int v = 0; v < 4; v++) acc[i][j][v] = 0.0f;

        auto issue = [&](int c) {
            const int s = c % STAGES;
            const int k0 = c * BKH;
            const uint32_t abase = sb + s * STAGE_BYTES;
            const uint32_t bbase = abase + A_BYTES;
#pragma unroll
            for (int i = 0; i < 8; i++) {
                int id = i * 128 + tid;
                int row = id >> 3, c8 = id & 7;
                cp_async16(abase + swz(row, c8),
                           A + (size_t)(bm + row) * lda + k0 + c8 * 8);
            }
            if (VB) {
                // V natural layout: 64 token-rows x 256B (128 d-cols)
#pragma unroll
                for (int i = 0; i < 8; i++) {
                    int id = i * 128 + tid;
                    int row = id >> 4, c16 = id & 15;
                    cp_async16(bbase + swz256(row, c16),
                               Bp + (size_t)(k0 + row) * ldb + bn + c16 * 8);
                }
            } else {
#pragma unroll
                for (int i = 0; i < 8; i++) {
                    int id = i * 128 + tid;
                    int row = id >> 3, c8 = id & 7;
                    cp_async16(bbase + swz(row, c8),
                               Bp + (size_t)(bn + row) * ldb + k0 + c8 * 8);
                }
            }
            cp_commit();
        };

        // all warps done reading previous tile's smem before refill
        __syncthreads();

        issue(0);
        issue(1);

        for (int c = 0; c < nch; c++) {
            if (c + 1 < nch) cp_wait<1>(); else cp_wait<0>();
            __syncthreads();
            if (c + 2 < nch) issue(c + 2);

            const uint32_t abase = sb + (c % STAGES) * STAGE_BYTES;
            const uint32_t bbase = abase + A_BYTES;

#pragma unroll
            for (int ks = 0; ks < 4; ks++) {
                uint32_t af[4][4];
#pragma unroll
                for (int mt = 0; mt < 4; mt++) {
                    int row = wm + mt * 16 + (lane & 15);
                    int c8  = 2 * ks + (lane >> 4);
                    ldmatrix_x4(af[mt][0], af[mt][1], af[mt][2], af[mt][3],
                                abase + swz(row, c8));
                }
                uint32_t bf[4][4];
#pragma unroll
                for (int p = 0; p < 4; p++) {
                    if (VB) {
                        // trans: stored rows = k (tokens), cols = n (d)
                        int krow = ks * 16 + (lane & 7) + (((lane >> 3) & 1) << 3);
                        int c16  = (wn >> 3) + 2 * p + (lane >> 4);
                        ldmatrix_x4_trans(bf[p][0], bf[p][1], bf[p][2], bf[p][3],
                                          bbase + swz256(krow, c16));
                    } else {
                        int row = wn + p * 16 + (lane & 7) + ((lane >> 4) << 3);
                        int c8  = 2 * ks + ((lane >> 3) & 1);
                        ldmatrix_x4(bf[p][0], bf[p][1], bf[p][2], bf[p][3],
                                    bbase + swz(row, c8));
                    }
                }
#pragma unroll
                for (int mt = 0; mt < 4; mt++)
#pragma unroll
                    for (int p = 0; p < 4; p++) {
                        mma_f16(acc[mt][2 * p],     af[mt], bf[p][0], bf[p][1]);
                        mma_f16(acc[mt][2 * p + 1], af[mt], bf[p][2], bf[p][3]);
                    }
            }
        }

        // epilogue
        const int r0 = lane >> 2, cc = (lane & 3) * 2;
#pragma unroll
        for (int mt = 0; mt < 4; mt++) {
            const int row = bm + wm + mt * 16 + r0;
            float inv0 = 1.0f, inv1 = 1.0f;
            if (MODE == 2) { inv0 = 1.0f / aux[row]; inv1 = 1.0f / aux[row + 8]; }
            float s0 = 0.0f, s1 = 0.0f;
#pragma unroll
            for (int nt = 0; nt < 8; nt++) {
                const int col = bn + wn + nt * 8 + cc;
                float v0 = acc[mt][nt][0] * alpha;
                float v1 = acc[mt][nt][1] * alpha;
                float v2 = acc[mt][nt][2] * alpha;
                float v3 = acc[mt][nt][3] * alpha;
                if (MODE == 0) {
                    float b0 = aux[col], b1 = aux[col + 1];
                    v0 += b0; v1 += b1; v2 += b0; v3 += b1;
                    __half* C = (__half*)Cv;
                    *reinterpret_cast<__half2*>(C + (size_t)row * ldc + col) = __floats2half2_rn(v0, v1);
                    *reinterpret_cast<__half2*>(C + (size_t)(row + 8) * ldc + col) = __floats2half2_rn(v2, v3);
                } else if (MODE == 1) {
                    v0 = __expf(v0); v1 = __expf(v1); v2 = __expf(v2); v3 = __expf(v3);
                    s0 += v0 + v1;  s1 += v2 + v3;
                    __half* C = (__half*)Cv;
                    *reinterpret_cast<__half2*>(C + (size_t)row * ldc + col) = __floats2half2_rn(v0, v1);
                    *reinterpret_cast<__half2*>(C + (size_t)(row + 8) * ldc + col) = __floats2half2_rn(v2, v3);
                } else {
                    float* C = (float*)Cv;
                    *reinterpret_cast<float2*>(C + (size_t)row * ldc + col) =
                        make_float2(v0 * inv0, v1 * inv0);
                    *reinterpret_cast<float2*>(C + (size_t)(row + 8) * ldc + col) =
                        make_float2(v2 * inv1, v3 * inv1);
                }
            }
            if (MODE == 1) {
                s0 += __shfl_xor_sync(~0u, s0, 1); s0 += __shfl_xor_sync(~0u, s0, 2);
                s1 += __shfl_xor_sync(~0u, s1, 1); s1 += __shfl_xor_sync(~0u, s1, 2);
                if ((lane & 3) == 0) {
                    const int part = tn * 2 + (warp & 1);
                    rsp[(size_t)row * NPART + part] = s0;
                    rsp[(size_t)(row + 8) * NPART + part] = s1;
                }
            }
        }
    }
}

// ---------------------------------------------------------------------------
// Fused prep (one launch): x->half, 3 W transposes (f32->half), bias concat.
// ---------------------------------------------------------------------------
__global__ __launch_bounds__(256)
void prep_kernel(const float* __restrict__ x,
                 const float* __restrict__ Wq, const float* __restrict__ Wk,
                 const float* __restrict__ Wv,
                 const float* __restrict__ bq, const float* __restrict__ bk,
                 const float* __restrict__ bv,
                 __half* __restrict__ Xh, __half* __restrict__ Wt,
                 float* __restrict__ bcat)
{
    const int bid = blockIdx.x;
    const int tid = threadIdx.x;

    if (bid < 3072) {
        __shared__ float t[32][33];
        const int which = bid >> 10;
        const int tile  = bid & 1023;
        const int bx = (tile & 31) * 32;
        const int by = (tile >> 5) * 32;
        const float* W = (which == 0) ? Wq : (which == 1) ? Wk : Wv;
        __half* out = Wt + (size_t)which * DMODEL * DMODEL;
        const int xl = tid & 31, yl = tid >> 5;
#pragma unroll
        for (int i = yl; i < 32; i += 8)
            t[i][xl] = W[(size_t)(by + i) * DMODEL + bx + xl];
        __syncthreads();
#pragma unroll
        for (int i = yl; i < 32; i += 8)
            out[(size_t)(bx + i) * DMODEL + by + xl] = __float2half_rn(t[xl][i]);
    } else if (bid < 4096) {
        const int n4 = NTOK * DMODEL / 4;
        int i = (bid - 3072) * 256 + tid;
        for (; i < n4; i += 1024 * 256) {
            float4 v = reinterpret_cast<const float4*>(x)[i];
            __half2* o = reinterpret_cast<__half2*>(Xh) + 2 * i;
            o[0] = __floats2half2_rn(v.x, v.y);
            o[1] = __floats2half2_rn(v.z, v.w);
        }
    } else {
        for (int i = tid; i < D3; i += 256) {
            float v = (i < DMODEL) ? bq[i]
                    : (i < 2 * DMODEL) ? bk[i - DMODEL]
                    : bv[i - 2 * DMODEL];
            bcat[i] = v;
        }
    }
}

__global__ __launch_bounds__(256)
void rowsum_reduce_kernel(const float* __restrict__ rsp, float* __restrict__ rs)
{
    int row = blockIdx.x * 256 + threadIdx.x;
    if (row < NTOK) {
        float s = 0.0f;
#pragma unroll 16
        for (int i = 0; i < NPART; i++) s += rsp[(size_t)row * NPART + i];
        rs[row] = s;
    }
}

// ---------------------------------------------------------------------------
extern "C" void kernel_launch(void* const* d_in, const int* in_sizes, int n_in,
                              void* d_out, int out_size)
{
    const float* x  = (const float*)d_in[0];
    const float* Wq = (const float*)d_in[1];
    const float* Wk = (const float*)d_in[2];
    const float* Wv = (const float*)d_in[3];
    const float* bq = (const float*)d_in[4];
    const float* bk = (const float*)d_in[5];
    const float* bv = (const float*)d_in[6];
    float* out = (float*)d_out;

    __half *Xh, *Wt, *QKV, *E;
    float *bcat, *rsp, *rowsum;
    cudaGetSymbolAddress((void**)&Xh,     g_Xh);
    cudaGetSymbolAddress((void**)&Wt,     g_Wt);
    cudaGetSymbolAddress((void**)&bcat,   g_bcat);
    cudaGetSymbolAddress((void**)&QKV,    g_QKV);
    cudaGetSymbolAddress((void**)&E,      g_E);
    cudaGetSymbolAddress((void**)&rsp,    g_rsp);
    cudaGetSymbolAddress((void**)&rowsum, g_rowsum);

    const int M = NTOK, D = DMODEL;

    cudaFuncSetAttribute(hgemm_nt<0, false>, cudaFuncAttributeMaxDynamicSharedMemorySize, GEMM_SMEM);
    cudaFuncSetAttribute(hgemm_nt<1, false>, cudaFuncAttributeMaxDynamicSharedMemorySize, GEMM_SMEM);
    cudaFuncSetAttribute(hgemm_nt<2, true >, cudaFuncAttributeMaxDynamicSharedMemorySize, GEMM_SMEM);

    // 1. fused prep
    prep_kernel<<<4097, 256>>>(x, Wq, Wk, Wv, bq, bk, bv, Xh, Wt, bcat);

    // 2. fused QKV projection (persistent)
    hgemm_nt<0, false><<<PGRID, 128, GEMM_SMEM>>>(Xh, D, Wt, D, bcat, nullptr,
                                                  QKV, D3, M / BM, D3 / BN, D, D3, 1.0f);

    // 3. E = exp(Q K^T / 32), partial rowsums (persistent)
    hgemm_nt<1, false><<<PGRID, 128, GEMM_SMEM>>>(QKV + 0 * D, D3, QKV + 1 * D, D3,
                                                  nullptr, rsp, E, M,
                                                  M / BM, M / BN, D, M, 1.0f / 32.0f);

    // 4. reduce partials
    rowsum_reduce_kernel<<<(M + 255) / 256, 256>>>(rsp, rowsum);

    // 5. out = (E @ V) / rowsum  (V read in natural layout via ldmatrix.trans)
    hgemm_nt<2, true><<<PGRID, 128, GEMM_SMEM>>>(E, M, QKV + 2 * D, D3, rowsum, nullptr,
                                                 out, D, M / BM, D / BN, M, D, 1.0f);
}

// round 13
// speedup vs baseline: 1.1226x; 1.0284x over previous
#include <cuda_runtime.h>
#include <cuda_fp16.h>
#include <math.h>
#include <stdint.h>

#define NTOK 4096
#define DMODEL 1024
#define D3 (3 * DMODEL)
#define NPART 64   // partials per row = (NTOK/BN) tiles * 2 col-warps

// Scratch (no cudaMalloc allowed)
__device__ __half g_Xh[NTOK * DMODEL];
__device__ __half g_Wt[D3 * DMODEL];
__device__ float  g_bcat[D3];
__device__ __half g_QKV[NTOK * D3];
__device__ __half g_E[(size_t)NTOK * NTOK];
__device__ float  g_rsp[(size_t)NTOK * NPART];

// ---------------------------------------------------------------------------
__device__ __forceinline__ void cp_async16(uint32_t smem_addr, const void* gptr) {
    asm volatile("cp.async.cg.shared.global [%0], [%1], 16;\n"
                 :: "r"(smem_addr), "l"(gptr));
}
__device__ __forceinline__ void cp_commit() {
    asm volatile("cp.async.commit_group;\n");
}
template <int N>
__device__ __forceinline__ void cp_wait() {
    asm volatile("cp.async.wait_group %0;\n" :: "n"(N));
}

__device__ __forceinline__ void ldmatrix_x4(uint32_t& r0, uint32_t& r1,
                                            uint32_t& r2, uint32_t& r3,
                                            uint32_t addr) {
    asm volatile("ldmatrix.sync.aligned.m8n8.x4.shared.b16 {%0,%1,%2,%3}, [%4];"
                 : "=r"(r0), "=r"(r1), "=r"(r2), "=r"(r3) : "r"(addr));
}

__device__ __forceinline__ void ldmatrix_x4_trans(uint32_t& r0, uint32_t& r1,
                                                  uint32_t& r2, uint32_t& r3,
                                                  uint32_t addr) {
    asm volatile("ldmatrix.sync.aligned.m8n8.x4.trans.shared.b16 {%0,%1,%2,%3}, [%4];"
                 : "=r"(r0), "=r"(r1), "=r"(r2), "=r"(r3) : "r"(addr));
}

__device__ __forceinline__ void mma_f16(float (&d)[4], const uint32_t (&a)[4],
                                        uint32_t b0, uint32_t b1) {
    asm volatile(
        "mma.sync.aligned.m16n8k16.row.col.f32.f16.f16.f32 "
        "{%0,%1,%2,%3}, {%4,%5,%6,%7}, {%8,%9}, {%0,%1,%2,%3};"
        : "+f"(d[0]), "+f"(d[1]), "+f"(d[2]), "+f"(d[3])
        : "r"(a[0]), "r"(a[1]), "r"(a[2]), "r"(a[3]), "r"(b0), "r"(b1));
}

// ---------------------------------------------------------------------------
// Persistent fp16 GEMM (128 thr, 4 warps, 64x64 warp tiles, CTA tile 128x128,
// BK=64, 3 stages, 2 CTAs/SM, 296 persistent CTAs).
// MODE 0: +bias half out. MODE 1: exp() half out + partial rowsums.
// MODE 2: f32 out scaled by 1/rowsum, rowsum reduced in-kernel from rsp.
// VB=false: B' is [N,K] k-major (NT). VB=true: B is [K,N] natural (V, trans).
// ---------------------------------------------------------------------------
#define BM 128
#define BN 128
#define BKH 64
#define A_BYTES (BM * 128)
#define B_BYTES (BN * 128)
#define STAGE_BYTES (A_BYTES + B_BYTES)     // 32768
#define STAGES 3
#define GEMM_SMEM (STAGES * STAGE_BYTES)    // 98304
#define PGRID 296

__device__ __forceinline__ uint32_t swz(int row, int c8) {
    return (uint32_t)(row * 128 + ((c8 ^ (row & 7)) << 4));
}
// 256-byte-row swizzle (for natural-layout V tiles: 64 k-rows x 256B)
__device__ __forceinline__ uint32_t swz256(int row, int c16) {
    return (uint32_t)(row * 256 + ((c16 ^ (row & 7)) << 4));
}

template <int MODE, bool VB>
__global__ __launch_bounds__(128, 2)
void hgemm_nt(const __half* __restrict__ A, int lda,
              const __half* __restrict__ Bp, int ldb,
              const float* __restrict__ aux,      // bias (MODE 0)
              float* __restrict__ rsp,            // partial rowsums (MODE 1 write, MODE 2 read)
              void* __restrict__ Cv, int ldc,
              int nbm, int nbn, int K, int N, float alpha)
{
    extern __shared__ __align__(1024) char smem[];
    const uint32_t sb = (uint32_t)__cvta_generic_to_shared(smem);
    const int tid = threadIdx.x, lane = tid & 31, warp = tid >> 5;
    const int wm = (warp >> 1) * 64, wn = (warp & 1) * 64;
    const int nch = K / BKH;
    const int ntiles = nbm * nbn;

    for (int t = blockIdx.x; t < ntiles; t += gridDim.x) {
        const int bm = (t / nbn) * BM;
        const int tn = t % nbn;
        const int bn = tn * BN;

        float acc[4][8][4];
#pragma unroll
        for (int i = 0; i < 4; i++)
#pragma unroll
            for (int j = 0; j < 8; j++)
#pragma unroll
                for (int v = 0; v < 4; v++) acc[i][j][v] = 0.0f;

        auto issue = [&](int c) {
            const int s = c % STAGES;
            const int k0 = c * BKH;
            const uint32_t abase = sb + s * STAGE_BYTES;
            const uint32_t bbase = abase + A_BYTES;
#pragma unroll
            for (int i = 0; i < 8; i++) {
                int id = i * 128 + tid;
                int row = id >> 3, c8 = id & 7;
                cp_async16(abase + swz(row, c8),
                           A + (size_t)(bm + row) * lda + k0 + c8 * 8);
            }
            if (VB) {
#pragma unroll
                for (int i = 0; i < 8; i++) {
                    int id = i * 128 + tid;
                    int row = id >> 4, c16 = id & 15;
                    cp_async16(bbase + swz256(row, c16),
                               Bp + (size_t)(k0 + row) * ldb + bn + c16 * 8);
                }
            } else {
#pragma unroll
                for (int i = 0; i < 8; i++) {
                    int id = i * 128 + tid;
                    int row = id >> 3, c8 = id & 7;
                    cp_async16(bbase + swz(row, c8),
                               Bp + (size_t)(bn + row) * ldb + k0 + c8 * 8);
                }
            }
            cp_commit();
        };

        // all warps done reading previous tile's smem before refill
        __syncthreads();

        issue(0);
        issue(1);

        // MODE 2: reduce this tile's row sums from partials while loads fly.
        // 4 lanes share each accumulator row; each sums 16 partials (4xfloat4),
        // then combines via shfl within the 4-lane group. Deterministic order.
        float invs[4][2];
        if (MODE == 2) {
#pragma unroll
            for (int mt = 0; mt < 4; mt++) {
#pragma unroll
                for (int h = 0; h < 2; h++) {
                    const int row = bm + wm + mt * 16 + (lane >> 2) + h * 8;
                    const float4* p = reinterpret_cast<const float4*>(
                        rsp + (size_t)row * NPART) + (lane & 3) * 4;
                    float s = 0.0f;
#pragma unroll
                    for (int i = 0; i < 4; i++) {
                        float4 v = p[i];
                        s += v.x + v.y + v.z + v.w;
                    }
                    s += __shfl_xor_sync(~0u, s, 1);
                    s += __shfl_xor_sync(~0u, s, 2);
                    invs[mt][h] = 1.0f / s;
                }
            }
        }

        for (int c = 0; c < nch; c++) {
            if (c + 1 < nch) cp_wait<1>(); else cp_wait<0>();
            __syncthreads();
            if (c + 2 < nch) issue(c + 2);

            const uint32_t abase = sb + (c % STAGES) * STAGE_BYTES;
            const uint32_t bbase = abase + A_BYTES;

#pragma unroll
            for (int ks = 0; ks < 4; ks++) {
                uint32_t af[4][4];
#pragma unroll
                for (int mt = 0; mt < 4; mt++) {
                    int row = wm + mt * 16 + (lane & 15);
                    int c8  = 2 * ks + (lane >> 4);
                    ldmatrix_x4(af[mt][0], af[mt][1], af[mt][2], af[mt][3],
                                abase + swz(row, c8));
                }
                uint32_t bf[4][4];
#pragma unroll
                for (int p = 0; p < 4; p++) {
                    if (VB) {
                        int krow = ks * 16 + (lane & 7) + (((lane >> 3) & 1) << 3);
                        int c16  = (wn >> 3) + 2 * p + (lane >> 4);
                        ldmatrix_x4_trans(bf[p][0], bf[p][1], bf[p][2], bf[p][3],
                                          bbase + swz256(krow, c16));
                    } else {
                        int row = wn + p * 16 + (lane & 7) + ((lane >> 4) << 3);
                        int c8  = 2 * ks + ((lane >> 3) & 1);
                        ldmatrix_x4(bf[p][0], bf[p][1], bf[p][2], bf[p][3],
                                    bbase + swz(row, c8));
                    }
                }
#pragma unroll
                for (int mt = 0; mt < 4; mt++)
#pragma unroll
                    for (int p = 0; p < 4; p++) {
                        mma_f16(acc[mt][2 * p],     af[mt], bf[p][0], bf[p][1]);
                        mma_f16(acc[mt][2 * p + 1], af[mt], bf[p][2], bf[p][3]);
                    }
            }
        }

        // epilogue
        const int r0 = lane >> 2, cc = (lane & 3) * 2;
#pragma unroll
        for (int mt = 0; mt < 4; mt++) {
            const int row = bm + wm + mt * 16 + r0;
            float s0 = 0.0f, s1 = 0.0f;
#pragma unroll
            for (int nt = 0; nt < 8; nt++) {
                const int col = bn + wn + nt * 8 + cc;
                float v0 = acc[mt][nt][0] * alpha;
                float v1 = acc[mt][nt][1] * alpha;
                float v2 = acc[mt][nt][2] * alpha;
                float v3 = acc[mt][nt][3] * alpha;
                if (MODE == 0) {
                    float b0 = aux[col], b1 = aux[col + 1];
                    v0 += b0; v1 += b1; v2 += b0; v3 += b1;
                    __half* C = (__half*)Cv;
                    *reinterpret_cast<__half2*>(C + (size_t)row * ldc + col) = __floats2half2_rn(v0, v1);
                    *reinterpret_cast<__half2*>(C + (size_t)(row + 8) * ldc + col) = __floats2half2_rn(v2, v3);
                } else if (MODE == 1) {
                    v0 = __expf(v0); v1 = __expf(v1); v2 = __expf(v2); v3 = __expf(v3);
                    s0 += v0 + v1;  s1 += v2 + v3;
                    __half* C = (__half*)Cv;
                    *reinterpret_cast<__half2*>(C + (size_t)row * ldc + col) = __floats2half2_rn(v0, v1);
                    *reinterpret_cast<__half2*>(C + (size_t)(row + 8) * ldc + col) = __floats2half2_rn(v2, v3);
                } else {
                    float* C = (float*)Cv;
                    *reinterpret_cast<float2*>(C + (size_t)row * ldc + col) =
                        make_float2(v0 * invs[mt][0], v1 * invs[mt][0]);
                    *reinterpret_cast<float2*>(C + (size_t)(row + 8) * ldc + col) =
                        make_float2(v2 * invs[mt][1], v3 * invs[mt][1]);
                }
            }
            if (MODE == 1) {
                s0 += __shfl_xor_sync(~0u, s0, 1); s0 += __shfl_xor_sync(~0u, s0, 2);
                s1 += __shfl_xor_sync(~0u, s1, 1); s1 += __shfl_xor_sync(~0u, s1, 2);
                if ((lane & 3) == 0) {
                    const int part = tn * 2 + (warp & 1);
                    rsp[(size_t)row * NPART + part] = s0;
                    rsp[(size_t)(row + 8) * NPART + part] = s1;
                }
            }
        }
    }
}

// ---------------------------------------------------------------------------
// Fused prep (one launch): x->half, 3 W transposes (f32->half), bias concat.
// ---------------------------------------------------------------------------
__global__ __launch_bounds__(256)
void prep_kernel(const float* __restrict__ x,
                 const float* __restrict__ Wq, const float* __restrict__ Wk,
                 const float* __restrict__ Wv,
                 const float* __restrict__ bq, const float* __restrict__ bk,
                 const float* __restrict__ bv,
                 __half* __restrict__ Xh, __half* __restrict__ Wt,
                 float* __restrict__ bcat)
{
    const int bid = blockIdx.x;
    const int tid = threadIdx.x;

    if (bid < 3072) {
        __shared__ float t[32][33];
        const int which = bid >> 10;
        const int tile  = bid & 1023;
        const int bx = (tile & 31) * 32;
        const int by = (tile >> 5) * 32;
        const float* W = (which == 0) ? Wq : (which == 1) ? Wk : Wv;
        __half* out = Wt + (size_t)which * DMODEL * DMODEL;
        const int xl = tid & 31, yl = tid >> 5;
#pragma unroll
        for (int i = yl; i < 32; i += 8)
            t[i][xl] = W[(size_t)(by + i) * DMODEL + bx + xl];
        __syncthreads();
#pragma unroll
        for (int i = yl; i < 32; i += 8)
            out[(size_t)(bx + i) * DMODEL + by + xl] = __float2half_rn(t[xl][i]);
    } else if (bid < 4096) {
        const int n4 = NTOK * DMODEL / 4;
        int i = (bid - 3072) * 256 + tid;
        for (; i < n4; i += 1024 * 256) {
            float4 v = reinterpret_cast<const float4*>(x)[i];
            __half2* o = reinterpret_cast<__half2*>(Xh) + 2 * i;
            o[0] = __floats2half2_rn(v.x, v.y);
            o[1] = __floats2half2_rn(v.z, v.w);
        }
    } else {
        for (int i = tid; i < D3; i += 256) {
            float v = (i < DMODEL) ? bq[i]
                    : (i < 2 * DMODEL) ? bk[i - DMODEL]
                    : bv[i - 2 * DMODEL];
            bcat[i] = v;
        }
    }
}

// ---------------------------------------------------------------------------
extern "C" void kernel_launch(void* const* d_in, const int* in_sizes, int n_in,
                              void* d_out, int out_size)
{
    const float* x  = (const float*)d_in[0];
    const float* Wq = (const float*)d_in[1];
    const float* Wk = (const float*)d_in[2];
    const float* Wv = (const float*)d_in[3];
    const float* bq = (const float*)d_in[4];
    const float* bk = (const float*)d_in[5];
    const float* bv = (const float*)d_in[6];
    float* out = (float*)d_out;

    __half *Xh, *Wt, *QKV, *E;
    float *bcat, *rsp;
    cudaGetSymbolAddress((void**)&Xh,   g_Xh);
    cudaGetSymbolAddress((void**)&Wt,   g_Wt);
    cudaGetSymbolAddress((void**)&bcat, g_bcat);
    cudaGetSymbolAddress((void**)&QKV,  g_QKV);
    cudaGetSymbolAddress((void**)&E,    g_E);
    cudaGetSymbolAddress((void**)&rsp,  g_rsp);

    const int M = NTOK, D = DMODEL;

    cudaFuncSetAttribute(hgemm_nt<0, false>, cudaFuncAttributeMaxDynamicSharedMemorySize, GEMM_SMEM);
    cudaFuncSetAttribute(hgemm_nt<1, false>, cudaFuncAttributeMaxDynamicSharedMemorySize, GEMM_SMEM);
    cudaFuncSetAttribute(hgemm_nt<2, true >, cudaFuncAttributeMaxDynamicSharedMemorySize, GEMM_SMEM);

    // 1. fused prep
    prep_kernel<<<4097, 256>>>(x, Wq, Wk, Wv, bq, bk, bv, Xh, Wt, bcat);

    // 2. fused QKV projection (persistent)
    hgemm_nt<0, false><<<PGRID, 128, GEMM_SMEM>>>(Xh, D, Wt, D, bcat, nullptr,
                                                  QKV, D3, M / BM, D3 / BN, D, D3, 1.0f);

    // 3. E = exp(Q K^T / 32), partial rowsums (persistent)
    hgemm_nt<1, false><<<PGRID, 128, GEMM_SMEM>>>(QKV + 0 * D, D3, QKV + 1 * D, D3,
                                                  nullptr, rsp, E, M,
                                                  M / BM, M / BN, D, M, 1.0f / 32.0f);

    // 4. out = (E @ V) / rowsum  (rowsum reduced in-kernel from partials)
    hgemm_nt<2, true><<<PGRID, 128, GEMM_SMEM>>>(E, M, QKV + 2 * D, D3, nullptr, rsp,
                                                 out, D, M / BM, D / BN, M, D, 1.0f);
}

// round 14
// speedup vs baseline: 1.1372x; 1.0129x over previous
#include <cuda_runtime.h>
#include <cuda_fp16.h>
#include <math.h>
#include <stdint.h>

#define NTOK 4096
#define DMODEL 1024
#define D3 (3 * DMODEL)
#define NPART 64   // partials per row = (NTOK/BN) tiles * 2 col-warps

// Scratch (no cudaMalloc allowed)
__device__ __half g_Xh[NTOK * DMODEL];
__device__ __half g_Wt[D3 * DMODEL];
__device__ float  g_bcat[D3];
__device__ __half g_QKV[NTOK * D3];
__device__ __half g_E[(size_t)NTOK * NTOK];
__device__ float  g_rsp[(size_t)NTOK * NPART];

// ---------------------------------------------------------------------------
__device__ __forceinline__ void cp_async16(uint32_t smem_addr, const void* gptr) {
    asm volatile("cp.async.cg.shared.global [%0], [%1], 16;\n"
                 :: "r"(smem_addr), "l"(gptr));
}
__device__ __forceinline__ void cp_commit() {
    asm volatile("cp.async.commit_group;\n");
}
template <int N>
__device__ __forceinline__ void cp_wait() {
    asm volatile("cp.async.wait_group %0;\n" :: "n"(N));
}

__device__ __forceinline__ void ldmatrix_x4(uint32_t& r0, uint32_t& r1,
                                            uint32_t& r2, uint32_t& r3,
                                            uint32_t addr) {
    asm volatile("ldmatrix.sync.aligned.m8n8.x4.shared.b16 {%0,%1,%2,%3}, [%4];"
                 : "=r"(r0), "=r"(r1), "=r"(r2), "=r"(r3) : "r"(addr));
}

__device__ __forceinline__ void ldmatrix_x4_trans(uint32_t& r0, uint32_t& r1,
                                                  uint32_t& r2, uint32_t& r3,
                                                  uint32_t addr) {
    asm volatile("ldmatrix.sync.aligned.m8n8.x4.trans.shared.b16 {%0,%1,%2,%3}, [%4];"
                 : "=r"(r0), "=r"(r1), "=r"(r2), "=r"(r3) : "r"(addr));
}

__device__ __forceinline__ void mma_f16(float (&d)[4], const uint32_t (&a)[4],
                                        uint32_t b0, uint32_t b1) {
    asm volatile(
        "mma.sync.aligned.m16n8k16.row.col.f32.f16.f16.f32 "
        "{%0,%1,%2,%3}, {%4,%5,%6,%7}, {%8,%9}, {%0,%1,%2,%3};"
        : "+f"(d[0]), "+f"(d[1]), "+f"(d[2]), "+f"(d[3])
        : "r"(a[0]), "r"(a[1]), "r"(a[2]), "r"(a[3]), "r"(b0), "r"(b1));
}

// ---------------------------------------------------------------------------
// Persistent fp16 GEMM (128 thr, 4 warps, 64x64 warp tiles, CTA tile 128x128,
// BK=64, 3 stages, 2 CTAs/SM, 296 persistent CTAs). Chunk body uses
// fragment-level software pipelining (af double-buffered across ks, bf
// prefetched under MMA batches).
// MODE 0: +bias half out. MODE 1: exp() half out + partial rowsums.
// MODE 2: f32 out scaled by 1/rowsum, rowsum reduced in-kernel from rsp.
// VB=false: B' is [N,K] k-major (NT). VB=true: B is [K,N] natural (V, trans).
// ---------------------------------------------------------------------------
#define BM 128
#define BN 128
#define BKH 64
#define A_BYTES (BM * 128)
#define B_BYTES (BN * 128)
#define STAGE_BYTES (A_BYTES + B_BYTES)     // 32768
#define STAGES 3
#define GEMM_SMEM (STAGES * STAGE_BYTES)    // 98304
#define PGRID 296

__device__ __forceinline__ uint32_t swz(int row, int c8) {
    return (uint32_t)(row * 128 + ((c8 ^ (row & 7)) << 4));
}
// 256-byte-row swizzle (for natural-layout V tiles: 64 k-rows x 256B)
__device__ __forceinline__ uint32_t swz256(int row, int c16) {
    return (uint32_t)(row * 256 + ((c16 ^ (row & 7)) << 4));
}

template <int MODE, bool VB>
__global__ __launch_bounds__(128, 2)
void hgemm_nt(const __half* __restrict__ A, int lda,
              const __half* __restrict__ Bp, int ldb,
              const float* __restrict__ aux,      // bias (MODE 0)
              float* __restrict__ rsp,            // partials (MODE 1 wr, MODE 2 rd)
              void* __restrict__ Cv, int ldc,
              int nbm, int nbn, int K, int N, float alpha)
{
    extern __shared__ __align__(1024) char smem[];
    const uint32_t sb = (uint32_t)__cvta_generic_to_shared(smem);
    const int tid = threadIdx.x, lane = tid & 31, warp = tid >> 5;
    const int wm = (warp >> 1) * 64, wn = (warp & 1) * 64;
    const int nch = K / BKH;
    const int ntiles = nbm * nbn;

    for (int t = blockIdx.x; t < ntiles; t += gridDim.x) {
        const int bm = (t / nbn) * BM;
        const int tn = t % nbn;
        const int bn = tn * BN;

        float acc[4][8][4];
#pragma unroll
        for (int i = 0; i < 4; i++)
#pragma unroll
            for (int j = 0; j < 8; j++)
#pragma unroll
                for (int v = 0; v < 4; v++) acc[i][j][v] = 0.0f;

        auto issue = [&](int c) {
            const int s = c % STAGES;
            const int k0 = c * BKH;
            const uint32_t abase = sb + s * STAGE_BYTES;
            const uint32_t bbase = abase + A_BYTES;
#pragma unroll
            for (int i = 0; i < 8; i++) {
                int id = i * 128 + tid;
                int row = id >> 3, c8 = id & 7;
                cp_async16(abase + swz(row, c8),
                           A + (size_t)(bm + row) * lda + k0 + c8 * 8);
            }
            if (VB) {
#pragma unroll
                for (int i = 0; i < 8; i++) {
                    int id = i * 128 + tid;
                    int row = id >> 4, c16 = id & 15;
                    cp_async16(bbase + swz256(row, c16),
                               Bp + (size_t)(k0 + row) * ldb + bn + c16 * 8);
                }
            } else {
#pragma unroll
                for (int i = 0; i < 8; i++) {
                    int id = i * 128 + tid;
                    int row = id >> 3, c8 = id & 7;
                    cp_async16(bbase + swz(row, c8),
                               Bp + (size_t)(bn + row) * ldb + k0 + c8 * 8);
                }
            }
            cp_commit();
        };

        __syncthreads();   // previous tile's smem fully consumed

        issue(0);
        issue(1);

        // MODE 2: reduce this tile's row sums from partials while loads fly.
        float invs[4][2];
        if (MODE == 2) {
#pragma unroll
            for (int mt = 0; mt < 4; mt++) {
#pragma unroll
                for (int h = 0; h < 2; h++) {
                    const int row = bm + wm + mt * 16 + (lane >> 2) + h * 8;
                    const float4* p = reinterpret_cast<const float4*>(
                        rsp + (size_t)row * NPART) + (lane & 3) * 4;
                    float s = 0.0f;
#pragma unroll
                    for (int i = 0; i < 4; i++) {
                        float4 v = p[i];
                        s += v.x + v.y + v.z + v.w;
                    }
                    s += __shfl_xor_sync(~0u, s, 1);
                    s += __shfl_xor_sync(~0u, s, 2);
                    invs[mt][h] = 1.0f / s;
                }
            }
        }

        for (int c = 0; c < nch; c++) {
            if (c + 1 < nch) cp_wait<1>(); else cp_wait<0>();
            __syncthreads();
            if (c + 2 < nch) issue(c + 2);

            const uint32_t abase = sb + (c % STAGES) * STAGE_BYTES;
            const uint32_t bbase = abase + A_BYTES;

            uint32_t af[2][4][4];
            uint32_t bf[4][4];

            auto LA = [&](int buf, int ks) {
#pragma unroll
                for (int mt = 0; mt < 4; mt++) {
                    int row = wm + mt * 16 + (lane & 15);
                    int c8  = 2 * ks + (lane >> 4);
                    ldmatrix_x4(af[buf][mt][0], af[buf][mt][1],
                                af[buf][mt][2], af[buf][mt][3],
                                abase + swz(row, c8));
                }
            };
            auto LB = [&](int p, int ks) {
                if (VB) {
                    int krow = ks * 16 + (lane & 7) + (((lane >> 3) & 1) << 3);
                    int c16  = (wn >> 3) + 2 * p + (lane >> 4);
                    ldmatrix_x4_trans(bf[p][0], bf[p][1], bf[p][2], bf[p][3],
                                      bbase + swz256(krow, c16));
                } else {
                    int row = wn + p * 16 + (lane & 7) + ((lane >> 4) << 3);
                    int c8  = 2 * ks + ((lane >> 3) & 1);
                    ldmatrix_x4(bf[p][0], bf[p][1], bf[p][2], bf[p][3],
                                bbase + swz(row, c8));
                }
            };
            auto MM = [&](int buf, int p) {
#pragma unroll
                for (int mt = 0; mt < 4; mt++) {
                    mma_f16(acc[mt][2 * p],     af[buf][mt], bf[p][0], bf[p][1]);
                    mma_f16(acc[mt][2 * p + 1], af[buf][mt], bf[p][2], bf[p][3]);
                }
            };

            // software-pipelined chunk (round-11 consumer schedule)
            LA(0, 0); LB(0, 0);
#pragma unroll
            for (int ks = 0; ks < 4; ks++) {
                const int cur = ks & 1;
                LB(1, ks);  MM(cur, 0);
                LB(2, ks);  MM(cur, 1);
                if (ks < 3) LA(cur ^ 1, ks + 1);
                LB(3, ks);  MM(cur, 2);
                if (ks < 3) LB(0, ks + 1);
                MM(cur, 3);
            }
        }

        // epilogue
        const int r0 = lane >> 2, cc = (lane & 3) * 2;
#pragma unroll
        for (int mt = 0; mt < 4; mt++) {
            const int row = bm + wm + mt * 16 + r0;
            float s0 = 0.0f, s1 = 0.0f;
#pragma unroll
            for (int nt = 0; nt < 8; nt++) {
                const int col = bn + wn + nt * 8 + cc;
                float v0 = acc[mt][nt][0] * alpha;
                float v1 = acc[mt][nt][1] * alpha;
                float v2 = acc[mt][nt][2] * alpha;
                float v3 = acc[mt][nt][3] * alpha;
                if (MODE == 0) {
                    float b0 = aux[col], b1 = aux[col + 1];
                    v0 += b0; v1 += b1; v2 += b0; v3 += b1;
                    __half* C = (__half*)Cv;
                    *reinterpret_cast<__half2*>(C + (size_t)row * ldc + col) = __floats2half2_rn(v0, v1);
                    *reinterpret_cast<__half2*>(C + (size_t)(row + 8) * ldc + col) = __floats2half2_rn(v2, v3);
                } else if (MODE == 1) {
                    v0 = __expf(v0); v1 = __expf(v1); v2 = __expf(v2); v3 = __expf(v3);
                    s0 += v0 + v1;  s1 += v2 + v3;
                    __half* C = (__half*)Cv;
                    *reinterpret_cast<__half2*>(C + (size_t)row * ldc + col) = __floats2half2_rn(v0, v1);
                    *reinterpret_cast<__half2*>(C + (size_t)(row + 8) * ldc + col) = __floats2half2_rn(v2, v3);
                } else {
                    float* C = (float*)Cv;
                    *reinterpret_cast<float2*>(C + (size_t)row * ldc + col) =
                        make_float2(v0 * invs[mt][0], v1 * invs[mt][0]);
                    *reinterpret_cast<float2*>(C + (size_t)(row + 8) * ldc + col) =
                        make_float2(v2 * invs[mt][1], v3 * invs[mt][1]);
                }
            }
            if (MODE == 1) {
                s0 += __shfl_xor_sync(~0u, s0, 1); s0 += __shfl_xor_sync(~0u, s0, 2);
                s1 += __shfl_xor_sync(~0u, s1, 1); s1 += __shfl_xor_sync(~0u, s1, 2);
                if ((lane & 3) == 0) {
                    const int part = tn * 2 + (warp & 1);
                    rsp[(size_t)row * NPART + part] = s0;
                    rsp[(size_t)(row + 8) * NPART + part] = s1;
                }
            }
        }
    }
}

// ---------------------------------------------------------------------------
// Fused prep (one launch): x->half, 3 W transposes (f32->half), bias concat.
// ---------------------------------------------------------------------------
__global__ __launch_bounds__(256)
void prep_kernel(const float* __restrict__ x,
                 const float* __restrict__ Wq, const float* __restrict__ Wk,
                 const float* __restrict__ Wv,
                 const float* __restrict__ bq, const float* __restrict__ bk,
                 const float* __restrict__ bv,
                 __half* __restrict__ Xh, __half* __restrict__ Wt,
                 float* __restrict__ bcat)
{
    const int bid = blockIdx.x;
    const int tid = threadIdx.x;

    if (bid < 3072) {
        __shared__ float t[32][33];
        const int which = bid >> 10;
        const int tile  = bid & 1023;
        const int bx = (tile & 31) * 32;
        const int by = (tile >> 5) * 32;
        const float* W = (which == 0) ? Wq : (which == 1) ? Wk : Wv;
        __half* out = Wt + (size_t)which * DMODEL * DMODEL;
        const int xl = tid & 31, yl = tid >> 5;
#pragma unroll
        for (int i = yl; i < 32; i += 8)
            t[i][xl] = W[(size_t)(by + i) * DMODEL + bx + xl];
        __syncthreads();
#pragma unroll
        for (int i = yl; i < 32; i += 8)
            out[(size_t)(bx + i) * DMODEL + by + xl] = __float2half_rn(t[xl][i]);
    } else if (bid < 4096) {
        const int n4 = NTOK * DMODEL / 4;
        int i = (bid - 3072) * 256 + tid;
        for (; i < n4; i += 1024 * 256) {
            float4 v = reinterpret_cast<const float4*>(x)[i];
            __half2* o = reinterpret_cast<__half2*>(Xh) + 2 * i;
            o[0] = __floats2half2_rn(v.x, v.y);
            o[1] = __floats2half2_rn(v.z, v.w);
        }
    } else {
        for (int i = tid; i < D3; i += 256) {
            float v = (i < DMODEL) ? bq[i]
                    : (i < 2 * DMODEL) ? bk[i - DMODEL]
                    : bv[i - 2 * DMODEL];
            bcat[i] = v;
        }
    }
}

// ---------------------------------------------------------------------------
extern "C" void kernel_launch(void* const* d_in, const int* in_sizes, int n_in,
                              void* d_out, int out_size)
{
    const float* x  = (const float*)d_in[0];
    const float* Wq = (const float*)d_in[1];
    const float* Wk = (const float*)d_in[2];
    const float* Wv = (const float*)d_in[3];
    const float* bq = (const float*)d_in[4];
    const float* bk = (const float*)d_in[5];
    const float* bv = (const float*)d_in[6];
    float* out = (float*)d_out;

    __half *Xh, *Wt, *QKV, *E;
    float *bcat, *rsp;
    cudaGetSymbolAddress((void**)&Xh,   g_Xh);
    cudaGetSymbolAddress((void**)&Wt,   g_Wt);
    cudaGetSymbolAddress((void**)&bcat, g_bcat);
    cudaGetSymbolAddress((void**)&QKV,  g_QKV);
    cudaGetSymbolAddress((void**)&E,    g_E);
    cudaGetSymbolAddress((void**)&rsp,  g_rsp);

    const int M = NTOK, D = DMODEL;

    cudaFuncSetAttribute(hgemm_nt<0, false>, cudaFuncAttributeMaxDynamicSharedMemorySize, GEMM_SMEM);
    cudaFuncSetAttribute(hgemm_nt<1, false>, cudaFuncAttributeMaxDynamicSharedMemorySize, GEMM_SMEM);
    cudaFuncSetAttribute(hgemm_nt<2, true >, cudaFuncAttributeMaxDynamicSharedMemorySize, GEMM_SMEM);

    // 1. fused prep
    prep_kernel<<<4097, 256>>>(x, Wq, Wk, Wv, bq, bk, bv, Xh, Wt, bcat);

    // 2. fused QKV projection (persistent)
    hgemm_nt<0, false><<<PGRID, 128, GEMM_SMEM>>>(Xh, D, Wt, D, bcat, nullptr,
                                                  QKV, D3, M / BM, D3 / BN, D, D3, 1.0f);

    // 3. E = exp(Q K^T / 32), partial rowsums (persistent)
    hgemm_nt<1, false><<<PGRID, 128, GEMM_SMEM>>>(QKV + 0 * D, D3, QKV + 1 * D, D3,
                                                  nullptr, rsp, E, M,
                                                  M / BM, M / BN, D, M, 1.0f / 32.0f);

    // 4. out = (E @ V) / rowsum  (rowsum reduced in-kernel from partials)
    hgemm_nt<2, true><<<PGRID, 128, GEMM_SMEM>>>(E, M, QKV + 2 * D, D3, nullptr, rsp,
                                                 out, D, M / BM, D / BN, M, D, 1.0f);
}

// round 15
// speedup vs baseline: 1.1804x; 1.0381x over previous
#include <cuda_runtime.h>
#include <cuda_fp16.h>
#include <math.h>
#include <stdint.h>

#define NTOK 4096
#define DMODEL 1024
#define D3 (3 * DMODEL)
#define NPART 64   // partials per row = (NTOK/BN) tiles * 2 col-warps

// Scratch (no cudaMalloc allowed)
__device__ __half g_Xh[NTOK * DMODEL];
__device__ __half g_Wt[D3 * DMODEL];
__device__ float  g_bcat[D3];
__device__ __half g_QKV[NTOK * D3];
__device__ __half g_E[(size_t)NTOK * NTOK];
__device__ float  g_rsp[(size_t)NTOK * NPART];

// ---------------------------------------------------------------------------
__device__ __forceinline__ void cp_async16(uint32_t smem_addr, const void* gptr) {
    asm volatile("cp.async.cg.shared.global [%0], [%1], 16;\n"
                 :: "r"(smem_addr), "l"(gptr));
}
__device__ __forceinline__ void cp_commit() {
    asm volatile("cp.async.commit_group;\n");
}
template <int N>
__device__ __forceinline__ void cp_wait() {
    asm volatile("cp.async.wait_group %0;\n" :: "n"(N));
}

__device__ __forceinline__ void ldmatrix_x4(uint32_t& r0, uint32_t& r1,
                                            uint32_t& r2, uint32_t& r3,
                                            uint32_t addr) {
    asm volatile("ldmatrix.sync.aligned.m8n8.x4.shared.b16 {%0,%1,%2,%3}, [%4];"
                 : "=r"(r0), "=r"(r1), "=r"(r2), "=r"(r3) : "r"(addr));
}

__device__ __forceinline__ void ldmatrix_x4_trans(uint32_t& r0, uint32_t& r1,
                                                  uint32_t& r2, uint32_t& r3,
                                                  uint32_t addr) {
    asm volatile("ldmatrix.sync.aligned.m8n8.x4.trans.shared.b16 {%0,%1,%2,%3}, [%4];"
                 : "=r"(r0), "=r"(r1), "=r"(r2), "=r"(r3) : "r"(addr));
}

__device__ __forceinline__ void mma_f16(float (&d)[4], const uint32_t (&a)[4],
                                        uint32_t b0, uint32_t b1) {
    asm volatile(
        "mma.sync.aligned.m16n8k16.row.col.f32.f16.f16.f32 "
        "{%0,%1,%2,%3}, {%4,%5,%6,%7}, {%8,%9}, {%0,%1,%2,%3};"
        : "+f"(d[0]), "+f"(d[1]), "+f"(d[2]), "+f"(d[3])
        : "r"(a[0]), "r"(a[1]), "r"(a[2]), "r"(a[3]), "r"(b0), "r"(b1));
}

// ---------------------------------------------------------------------------
// Persistent fp16 GEMM (128 thr, 4 warps, 64x64 warp tiles, CTA tile 128x128,
// BK=64, 3 stages, 2 CTAs/SM, 296 persistent CTAs). Fragment-level software
// pipelining; cp.async prefetch issued mid-chunk (after first MMA batch) to
// spread the LSU burst; MODE-2 rowsum reduction in epilogue (no regs live
// across the mainloop).
// MODE 0: +bias half out. MODE 1: exp() half out + partial rowsums.
// MODE 2: f32 out scaled by 1/rowsum, rowsum reduced in-kernel from rsp.
// VB=false: B' is [N,K] k-major (NT). VB=true: B is [K,N] natural (V, trans).
// ---------------------------------------------------------------------------
#define BM 128
#define BN 128
#define BKH 64
#define A_BYTES (BM * 128)
#define B_BYTES (BN * 128)
#define STAGE_BYTES (A_BYTES + B_BYTES)     // 32768
#define STAGES 3
#define GEMM_SMEM (STAGES * STAGE_BYTES)    // 98304
#define PGRID 296

__device__ __forceinline__ uint32_t swz(int row, int c8) {
    return (uint32_t)(row * 128 + ((c8 ^ (row & 7)) << 4));
}
// 256-byte-row swizzle (for natural-layout V tiles: 64 k-rows x 256B)
__device__ __forceinline__ uint32_t swz256(int row, int c16) {
    return (uint32_t)(row * 256 + ((c16 ^ (row & 7)) << 4));
}

template <int MODE, bool VB>
__global__ __launch_bounds__(128, 2)
void hgemm_nt(const __half* __restrict__ A, int lda,
              const __half* __restrict__ Bp, int ldb,
              const float* __restrict__ aux,      // bias (MODE 0)
              float* __restrict__ rsp,            // partials (MODE 1 wr, MODE 2 rd)
              void* __restrict__ Cv, int ldc,
              int nbm, int nbn, int K, int N, float alpha)
{
    extern __shared__ __align__(1024) char smem[];
    const uint32_t sb = (uint32_t)__cvta_generic_to_shared(smem);
    const int tid = threadIdx.x, lane = tid & 31, warp = tid >> 5;
    const int wm = (warp >> 1) * 64, wn = (warp & 1) * 64;
    const int nch = K / BKH;
    const int ntiles = nbm * nbn;

    for (int t = blockIdx.x; t < ntiles; t += gridDim.x) {
        const int bm = (t / nbn) * BM;
        const int tn = t % nbn;
        const int bn = tn * BN;

        float acc[4][8][4];
#pragma unroll
        for (int i = 0; i < 4; i++)
#pragma unroll
            for (int j = 0; j < 8; j++)
#pragma unroll
                for (int v = 0; v < 4; v++) acc[i][j][v] = 0.0f;

        auto issue = [&](int c) {
            const int s = c % STAGES;
            const int k0 = c * BKH;
            const uint32_t abase = sb + s * STAGE_BYTES;
            const uint32_t bbase = abase + A_BYTES;
#pragma unroll
            for (int i = 0; i < 8; i++) {
                int id = i * 128 + tid;
                int row = id >> 3, c8 = id & 7;
                cp_async16(abase + swz(row, c8),
                           A + (size_t)(bm + row) * lda + k0 + c8 * 8);
            }
            if (VB) {
#pragma unroll
                for (int i = 0; i < 8; i++) {
                    int id = i * 128 + tid;
                    int row = id >> 4, c16 = id & 15;
                    cp_async16(bbase + swz256(row, c16),
                               Bp + (size_t)(k0 + row) * ldb + bn + c16 * 8);
                }
            } else {
#pragma unroll
                for (int i = 0; i < 8; i++) {
                    int id = i * 128 + tid;
                    int row = id >> 3, c8 = id & 7;
                    cp_async16(bbase + swz(row, c8),
                               Bp + (size_t)(bn + row) * ldb + k0 + c8 * 8);
                }
            }
            cp_commit();
        };

        __syncthreads();   // previous tile's smem fully consumed

        issue(0);
        issue(1);

        for (int c = 0; c < nch; c++) {
            if (c + 1 < nch) cp_wait<1>(); else cp_wait<0>();
            __syncthreads();

            const uint32_t abase = sb + (c % STAGES) * STAGE_BYTES;
            const uint32_t bbase = abase + A_BYTES;

            uint32_t af[2][4][4];
            uint32_t bf[4][4];

            auto LA = [&](int buf, int ks) {
#pragma unroll
                for (int mt = 0; mt < 4; mt++) {
                    int row = wm + mt * 16 + (lane & 15);
                    int c8  = 2 * ks + (lane >> 4);
                    ldmatrix_x4(af[buf][mt][0], af[buf][mt][1],
                                af[buf][mt][2], af[buf][mt][3],
                                abase + swz(row, c8));
                }
            };
            auto LB = [&](int p, int ks) {
                if (VB) {
                    int krow = ks * 16 + (lane & 7) + (((lane >> 3) & 1) << 3);
                    int c16  = (wn >> 3) + 2 * p + (lane >> 4);
                    ldmatrix_x4_trans(bf[p][0], bf[p][1], bf[p][2], bf[p][3],
                                      bbase + swz256(krow, c16));
                } else {
                    int row = wn + p * 16 + (lane & 7) + ((lane >> 4) << 3);
                    int c8  = 2 * ks + ((lane >> 3) & 1);
                    ldmatrix_x4(bf[p][0], bf[p][1], bf[p][2], bf[p][3],
                                bbase + swz(row, c8));
                }
            };
            auto MM = [&](int buf, int p) {
#pragma unroll
                for (int mt = 0; mt < 4; mt++) {
                    mma_f16(acc[mt][2 * p],     af[buf][mt], bf[p][0], bf[p][1]);
                    mma_f16(acc[mt][2 * p + 1], af[buf][mt], bf[p][2], bf[p][3]);
                }
            };

            // ks = 0 (peeled; prefetch of chunk c+2 issued after first batch
            // so the cp.async burst lands in the MMA shadow, not the barrier)
            LA(0, 0); LB(0, 0);
            LB(1, 0);  MM(0, 0);
            if (c + 2 < nch) issue(c + 2);
            LB(2, 0);  MM(0, 1);
            LA(1, 1);
            LB(3, 0);  MM(0, 2);
            LB(0, 1);  MM(0, 3);

#pragma unroll
            for (int ks = 1; ks < 4; ks++) {
                const int cur = ks & 1;
                LB(1, ks);  MM(cur, 0);
                LB(2, ks);  MM(cur, 1);
                if (ks < 3) LA(cur ^ 1, ks + 1);
                LB(3, ks);  MM(cur, 2);
                if (ks < 3) LB(0, ks + 1);
                MM(cur, 3);
            }
        }

        // epilogue
        const int r0 = lane >> 2, cc = (lane & 3) * 2;

        // MODE 2: reduce this tile's row sums from partials (deterministic).
        float invs[4][2];
        if (MODE == 2) {
#pragma unroll
            for (int mt = 0; mt < 4; mt++) {
#pragma unroll
                for (int h = 0; h < 2; h++) {
                    const int row = bm + wm + mt * 16 + (lane >> 2) + h * 8;
                    const float4* p = reinterpret_cast<const float4*>(
                        rsp + (size_t)row * NPART) + (lane & 3) * 4;
                    float s = 0.0f;
#pragma unroll
                    for (int i = 0; i < 4; i++) {
                        float4 v = p[i];
                        s += v.x + v.y + v.z + v.w;
                    }
                    s += __shfl_xor_sync(~0u, s, 1);
                    s += __shfl_xor_sync(~0u, s, 2);
                    invs[mt][h] = 1.0f / s;
                }
            }
        }

#pragma unroll
        for (int mt = 0; mt < 4; mt++) {
            const int row = bm + wm + mt * 16 + r0;
            float s0 = 0.0f, s1 = 0.0f;
#pragma unroll
            for (int nt = 0; nt < 8; nt++) {
                const int col = bn + wn + nt * 8 + cc;
                float v0 = acc[mt][nt][0];
                float v1 = acc[mt][nt][1];
                float v2 = acc[mt][nt][2];
                float v3 = acc[mt][nt][3];
                if (MODE == 0) {
                    float b0 = aux[col], b1 = aux[col + 1];
                    v0 += b0; v1 += b1; v2 += b0; v3 += b1;
                    __half* C = (__half*)Cv;
                    *reinterpret_cast<__half2*>(C + (size_t)row * ldc + col) = __floats2half2_rn(v0, v1);
                    *reinterpret_cast<__half2*>(C + (size_t)(row + 8) * ldc + col) = __floats2half2_rn(v2, v3);
                } else if (MODE == 1) {
                    v0 = __expf(v0 * alpha); v1 = __expf(v1 * alpha);
                    v2 = __expf(v2 * alpha); v3 = __expf(v3 * alpha);
                    s0 += v0 + v1;  s1 += v2 + v3;
                    __half* C = (__half*)Cv;
                    *reinterpret_cast<__half2*>(C + (size_t)row * ldc + col) = __floats2half2_rn(v0, v1);
                    *reinterpret_cast<__half2*>(C + (size_t)(row + 8) * ldc + col) = __floats2half2_rn(v2, v3);
                } else {
                    float* C = (float*)Cv;
                    *reinterpret_cast<float2*>(C + (size_t)row * ldc + col) =
                        make_float2(v0 * invs[mt][0], v1 * invs[mt][0]);
                    *reinterpret_cast<float2*>(C + (size_t)(row + 8) * ldc + col) =
                        make_float2(v2 * invs[mt][1], v3 * invs[mt][1]);
                }
            }
            if (MODE == 1) {
                s0 += __shfl_xor_sync(~0u, s0, 1); s0 += __shfl_xor_sync(~0u, s0, 2);
                s1 += __shfl_xor_sync(~0u, s1, 1); s1 += __shfl_xor_sync(~0u, s1, 2);
                if ((lane & 3) == 0) {
                    const int part = tn * 2 + (warp & 1);
                    rsp[(size_t)row * NPART + part] = s0;
                    rsp[(size_t)(row + 8) * NPART + part] = s1;
                }
            }
        }
    }
}

// ---------------------------------------------------------------------------
// Fused prep (one launch): x->half, 3 W transposes (f32->half), bias concat.
// ---------------------------------------------------------------------------
__global__ __launch_bounds__(256)
void prep_kernel(const float* __restrict__ x,
                 const float* __restrict__ Wq, const float* __restrict__ Wk,
                 const float* __restrict__ Wv,
                 const float* __restrict__ bq, const float* __restrict__ bk,
                 const float* __restrict__ bv,
                 __half* __restrict__ Xh, __half* __restrict__ Wt,
                 float* __restrict__ bcat)
{
    const int bid = blockIdx.x;
    const int tid = threadIdx.x;

    if (bid < 3072) {
        __shared__ float t[32][33];
        const int which = bid >> 10;
        const int tile  = bid & 1023;
        const int bx = (tile & 31) * 32;
        const int by = (tile >> 5) * 32;
        const float* W = (which == 0) ? Wq : (which == 1) ? Wk : Wv;
        __half* out = Wt + (size_t)which * DMODEL * DMODEL;
        const int xl = tid & 31, yl = tid >> 5;
#pragma unroll
        for (int i = yl; i < 32; i += 8)
            t[i][xl] = W[(size_t)(by + i) * DMODEL + bx + xl];
        __syncthreads();
#pragma unroll
        for (int i = yl; i < 32; i += 8)
            out[(size_t)(bx + i) * DMODEL + by + xl] = __float2half_rn(t[xl][i]);
    } else if (bid < 4096) {
        const int n4 = NTOK * DMODEL / 4;
        int i = (bid - 3072) * 256 + tid;
        for (; i < n4; i += 1024 * 256) {
            float4 v = reinterpret_cast<const float4*>(x)[i];
            __half2* o = reinterpret_cast<__half2*>(Xh) + 2 * i;
            o[0] = __floats2half2_rn(v.x, v.y);
            o[1] = __floats2half2_rn(v.z, v.w);
        }
    } else {
        for (int i = tid; i < D3; i += 256) {
            float v = (i < DMODEL) ? bq[i]
                    : (i < 2 * DMODEL) ? bk[i - DMODEL]
                    : bv[i - 2 * DMODEL];
            bcat[i] = v;
        }
    }
}

// ---------------------------------------------------------------------------
extern "C" void kernel_launch(void* const* d_in, const int* in_sizes, int n_in,
                              void* d_out, int out_size)
{
    const float* x  = (const float*)d_in[0];
    const float* Wq = (const float*)d_in[1];
    const float* Wk = (const float*)d_in[2];
    const float* Wv = (const float*)d_in[3];
    const float* bq = (const float*)d_in[4];
    const float* bk = (const float*)d_in[5];
    const float* bv = (const float*)d_in[6];
    float* out = (float*)d_out;

    __half *Xh, *Wt, *QKV, *E;
    float *bcat, *rsp;
    cudaGetSymbolAddress((void**)&Xh,   g_Xh);
    cudaGetSymbolAddress((void**)&Wt,   g_Wt);
    cudaGetSymbolAddress((void**)&bcat, g_bcat);
    cudaGetSymbolAddress((void**)&QKV,  g_QKV);
    cudaGetSymbolAddress((void**)&E,    g_E);
    cudaGetSymbolAddress((void**)&rsp,  g_rsp);

    const int M = NTOK, D = DMODEL;

    cudaFuncSetAttribute(hgemm_nt<0, false>, cudaFuncAttributeMaxDynamicSharedMemorySize, GEMM_SMEM);
    cudaFuncSetAttribute(hgemm_nt<1, false>, cudaFuncAttributeMaxDynamicSharedMemorySize, GEMM_SMEM);
    cudaFuncSetAttribute(hgemm_nt<2, true >, cudaFuncAttributeMaxDynamicSharedMemorySize, GEMM_SMEM);

    // 1. fused prep
    prep_kernel<<<4097, 256>>>(x, Wq, Wk, Wv, bq, bk, bv, Xh, Wt, bcat);

    // 2. fused QKV projection (persistent)
    hgemm_nt<0, false><<<PGRID, 128, GEMM_SMEM>>>(Xh, D, Wt, D, bcat, nullptr,
                                                  QKV, D3, M / BM, D3 / BN, D, D3, 1.0f);

    // 3. E = exp(Q K^T / 32), partial rowsums (persistent)
    hgemm_nt<1, false><<<PGRID, 128, GEMM_SMEM>>>(QKV + 0 * D, D3, QKV + 1 * D, D3,
                                                  nullptr, rsp, E, M,
                                                  M / BM, M / BN, D, M, 1.0f / 32.0f);

    // 4. out = (E @ V) / rowsum  (rowsum reduced in-kernel from partials)
    hgemm_nt<2, true><<<PGRID, 128, GEMM_SMEM>>>(E, M, QKV + 2 * D, D3, nullptr, rsp,
                                                 out, D, M / BM, D / BN, M, D, 1.0f);
}